// round 7
// baseline (speedup 1.0000x reference)
#include <cuda_runtime.h>
#include <cuda_fp16.h>
#include <cstdint>
#include <cstddef>

// Shapes: batch[16,1024,1024] -> M=16384,K=1024 ; W1[1024,1024] ; W2[1024,128]
// out[16,1024,1024] fp32.
static const int M_TOT = 16384;
static const int D_DIM = 1024;
static const int H_DIM = 1024;
static const int R_DIM = 128;
static const int L_DIM = 1024;
static const int B_DIM = 16;

// ---- scratch (__device__ globals; no runtime allocation allowed) ----
__device__ __align__(256) __half g_a_hi[(size_t)16384 * 1024];
__device__ __align__(256) __half g_h_hi[(size_t)16384 * 1024];
__device__ __align__(256) __half g_w1t_hi[(size_t)1024 * 1024];
__device__ __align__(256) __half g_w1t_lo[(size_t)1024 * 1024];
__device__ __align__(256) __half g_w2t_hi[(size_t)128 * 1024];
__device__ __align__(256) __half g_w2t_lo[(size_t)128 * 1024];
__device__ __align__(256) __half g_t_hi[(size_t)16384 * 128];
__device__ __align__(256) __half g_t_lo[(size_t)16384 * 128];
__device__ __align__(256) float g_sq[16384];

// ---------------- PTX helpers ----------------
__device__ __forceinline__ uint32_t smem_u32(const void* p) {
    uint32_t a;
    asm("{ .reg .u64 t; cvta.to.shared.u64 t, %1; cvt.u32.u64 %0, t; }" : "=r"(a) : "l"(p));
    return a;
}
__device__ __forceinline__ void cp16(uint32_t saddr, const void* g) {
    asm volatile("cp.async.cg.shared.global [%0], [%1], 16;" :: "r"(saddr), "l"(g));
}
__device__ __forceinline__ void cp_commit() {
    asm volatile("cp.async.commit_group;" ::: "memory");
}
__device__ __forceinline__ void ldsm4(uint32_t* r, uint32_t addr) {
    asm volatile("ldmatrix.sync.aligned.m8n8.x4.shared.b16 {%0,%1,%2,%3}, [%4];"
                 : "=r"(r[0]), "=r"(r[1]), "=r"(r[2]), "=r"(r[3]) : "r"(addr));
}
__device__ __forceinline__ void mma_f16(float* c, const uint32_t* a, const uint32_t* b) {
    asm volatile(
        "mma.sync.aligned.m16n8k16.row.col.f32.f16.f16.f32 "
        "{%0,%1,%2,%3}, {%4,%5,%6,%7}, {%8,%9}, {%0,%1,%2,%3};"
        : "+f"(c[0]), "+f"(c[1]), "+f"(c[2]), "+f"(c[3])
        : "r"(a[0]), "r"(a[1]), "r"(a[2]), "r"(a[3]), "r"(b[0]), "r"(b[1]));
}

// ---------------- unified tensor-core GEMM ------------------------
// acc = A @ B^T, fp16 split operands, fp32 accumulate.
// MODE 0 (GEMM1): CTA 128x256, warp 64x64, 2 products; C=relu(acc+bias)->half hi
// MODE 1 (GEMM2): CTA 128x128, warp 64x32, 2 products; C->hi/lo + row sumsq->Cf
// MODE 2 (DIST):  CTA 128x128, warp 64x32, 3 products;
//                 out = max(sq_i + sq_j - 2*acc, 0); bias = sq
// 8 warps: warp_m = wid&1 (2 x 64 rows), warp_n = wid>>1 (4 x WN cols).
// smem rows are 64B (one 32-fp16 k-chunk); 16B chunk sub of row r stored at
// sub' = (sub + (r>>1)) & 3 (conflict-free cp.async stores + ldmatrix reads).
template <int MODE>
__global__ __launch_bounds__(256, (MODE == 0) ? 1 : 2)
void mma_gemm(const __half* __restrict__ Ahi, const __half* __restrict__ Alo,
              const __half* __restrict__ Bhi, const __half* __restrict__ Blo,
              const float* __restrict__ bias,
              float* __restrict__ Cf,
              __half* __restrict__ Chi, __half* __restrict__ Clo,
              int K, int Ncols) {
    constexpr int WN   = (MODE == 0) ? 64 : 32;      // warp n-extent
    constexpr int NP   = WN / 16;                    // 16-col groups per warp
    constexpr int BN   = 4 * WN;                     // CTA n-extent
    constexpr int ASZ  = (MODE == 2) ? 16384 : 8192; // A bytes/stage
    constexpr int BSZ  = (MODE == 0) ? 32768 : 16384;
    constexpr int STG  = ASZ + BSZ;
    constexpr int NSTG = (MODE == 1) ? 4 : 3;
    constexpr int NITER = STG / 16 / 256;
    constexpr bool PROD3 = (MODE == 2);

    extern __shared__ char smem[];
    const uint32_t sbase = smem_u32(smem);
    float* sq_s = reinterpret_cast<float*>(smem + NSTG * STG);
    const int tid = threadIdx.x;
    const int lane = tid & 31;
    const int wid = tid >> 5;
    const int warp_m = wid & 1;
    const int warp_n = wid >> 1;

    const int mBase = blockIdx.y * 128;
    const int nBase = blockIdx.x * BN;
    const int zb = (MODE == 2) ? blockIdx.z : 0;
    const size_t zrow = (size_t)zb * 1024;
    const int NC = K >> 5;

    if (MODE == 1 && tid < 128) sq_s[tid] = 0.0f;

    float acc[4][2 * NP][4];
#pragma unroll
    for (int i = 0; i < 4; i++)
#pragma unroll
        for (int j = 0; j < 2 * NP; j++)
#pragma unroll
            for (int q = 0; q < 4; q++) acc[i][j][q] = 0.0f;

    auto load_chunk = [&](int c, int stg) {
        const int k0 = c << 5;
        const uint32_t sb = sbase + stg * STG;
#pragma unroll
        for (int it = 0; it < NITER; ++it) {
            const __half* src; uint32_t soff; int rb, rel;
            if (MODE == 0) {
                if (it < 2)      { src = Ahi; soff = 0;              rb = mBase; rel = tid + it * 256; }
                else if (it < 6) { src = Bhi; soff = ASZ;            rb = nBase; rel = tid + (it - 2) * 256; }
                else             { src = Blo; soff = ASZ + BSZ / 2;  rb = nBase; rel = tid + (it - 6) * 256; }
            } else if (MODE == 1) {
                if (it < 2)      { src = Ahi; soff = 0;              rb = mBase; rel = tid + it * 256; }
                else if (it < 4) { src = Bhi; soff = ASZ;            rb = nBase; rel = tid + (it - 2) * 256; }
                else             { src = Blo; soff = ASZ + BSZ / 2;  rb = nBase; rel = tid + (it - 4) * 256; }
            } else {
                if (it < 2)      { src = Ahi; soff = 0;              rb = mBase; rel = tid + it * 256; }
                else if (it < 4) { src = Alo; soff = 8192;           rb = mBase; rel = tid + (it - 2) * 256; }
                else if (it < 6) { src = Bhi; soff = ASZ;            rb = nBase; rel = tid + (it - 4) * 256; }
                else             { src = Blo; soff = ASZ + BSZ / 2;  rb = nBase; rel = tid + (it - 6) * 256; }
            }
            const int row = rel >> 2, sub = rel & 3;
            const size_t goff = (zrow + rb + row) * (size_t)K + k0 + sub * 8;
            const uint32_t dst = sb + soff + row * 64 + (((sub + (row >> 1)) & 3) << 4);
            cp16(dst, src + goff);
        }
    };

    load_chunk(0, 0); cp_commit();
#pragma unroll
    for (int s = 1; s < NSTG; ++s) {
        if (s < NC) load_chunk(s, s);
        cp_commit();
    }

    // ldmatrix per-lane components (swizzle base is fragment-invariant)
    const int a_row_l = lane & 15;
    const int a_sw = (lane >> 4) + (a_row_l >> 1);
    const int b_row_l = (lane & 7) + ((lane >> 4) << 3);
    const int b_sw = ((lane >> 3) & 1) + (b_row_l >> 1);

    for (int c = 0; c < NC; ++c) {
        if (NSTG == 4) asm volatile("cp.async.wait_group 2;" ::: "memory");
        else           asm volatile("cp.async.wait_group 1;" ::: "memory");
        __syncthreads();
        if (c + NSTG - 1 < NC) load_chunk(c + NSTG - 1, (c + NSTG - 1) % NSTG);
        cp_commit();
        const uint32_t base = sbase + (c % NSTG) * STG;
#pragma unroll
        for (int ks = 0; ks < 2; ++ks) {
            uint32_t Ah[4][4], Al[4][4];
#pragma unroll
            for (int mi = 0; mi < 4; ++mi) {
                const int row = warp_m * 64 + mi * 16 + a_row_l;
                const uint32_t addr = base + row * 64 + (((ks * 2 + a_sw) & 3) << 4);
                ldsm4(Ah[mi], addr);
                if (PROD3) ldsm4(Al[mi], addr + 8192);
            }
#pragma unroll
            for (int np = 0; np < NP; ++np) {
                uint32_t Bh[4], Bl[4];
                const int n = warp_n * WN + np * 16 + b_row_l;
                const uint32_t baddr = base + ASZ + n * 64 + (((ks * 2 + b_sw) & 3) << 4);
                ldsm4(Bh, baddr);
                ldsm4(Bl, baddr + BSZ / 2);
#pragma unroll
                for (int half = 0; half < 2; ++half) {
                    const uint32_t bh[2] = {Bh[half * 2], Bh[half * 2 + 1]};
                    const uint32_t bl[2] = {Bl[half * 2], Bl[half * 2 + 1]};
                    // product-major ordering: 4 independent MMAs between RAW pairs
#pragma unroll
                    for (int mi = 0; mi < 4; ++mi)
                        mma_f16(acc[mi][np * 2 + half], Ah[mi], bh);
#pragma unroll
                    for (int mi = 0; mi < 4; ++mi)
                        mma_f16(acc[mi][np * 2 + half], Ah[mi], bl);
                    if (PROD3) {
#pragma unroll
                        for (int mi = 0; mi < 4; ++mi)
                            mma_f16(acc[mi][np * 2 + half], Al[mi], bh);
                    }
                }
            }
        }
    }

    // ---------------- epilogue ----------------
    if (MODE == 2) {
        const float* sqg = bias + zb * 1024;
        float* Ob = Cf + (size_t)zb * 1024 * 1024;
#pragma unroll
        for (int mi = 0; mi < 4; ++mi) {
            const int r0 = mBase + warp_m * 64 + mi * 16 + (lane >> 2);
            const float sr0 = sqg[r0], sr1 = sqg[r0 + 8];
#pragma unroll
            for (int ni = 0; ni < 2 * NP; ++ni) {
                const int col = nBase + warp_n * WN + ni * 8 + 2 * (lane & 3);
                const float sc0 = sqg[col], sc1 = sqg[col + 1];
                const float* cc = acc[mi][ni];
                *reinterpret_cast<float2*>(Ob + (size_t)r0 * Ncols + col) =
                    make_float2(fmaxf(sr0 + sc0 - 2.0f * cc[0], 0.f),
                                fmaxf(sr0 + sc1 - 2.0f * cc[1], 0.f));
                *reinterpret_cast<float2*>(Ob + (size_t)(r0 + 8) * Ncols + col) =
                    make_float2(fmaxf(sr1 + sc0 - 2.0f * cc[2], 0.f),
                                fmaxf(sr1 + sc1 - 2.0f * cc[3], 0.f));
            }
        }
    } else {
#pragma unroll
        for (int mi = 0; mi < 4; ++mi) {
            const int r0 = mBase + warp_m * 64 + mi * 16 + (lane >> 2);
            float ss0 = 0.0f, ss1 = 0.0f;
#pragma unroll
            for (int ni = 0; ni < 2 * NP; ++ni) {
                const int col = nBase + warp_n * WN + ni * 8 + 2 * (lane & 3);
                const float bz0 = __ldg(&bias[col]), bz1 = __ldg(&bias[col + 1]);
                const float* cc = acc[mi][ni];
                const float v00 = fmaxf(cc[0] + bz0, 0.f), v01 = fmaxf(cc[1] + bz1, 0.f);
                const float v10 = fmaxf(cc[2] + bz0, 0.f), v11 = fmaxf(cc[3] + bz1, 0.f);
                if (MODE == 1) { ss0 += v00 * v00 + v01 * v01; ss1 += v10 * v10 + v11 * v11; }
                const __half h00 = __float2half_rn(v00), h01 = __float2half_rn(v01);
                const __half h10 = __float2half_rn(v10), h11 = __float2half_rn(v11);
                __half2 hp0 = __halves2half2(h00, h01);
                __half2 hp1 = __halves2half2(h10, h11);
                *reinterpret_cast<uint32_t*>(Chi + (size_t)r0 * Ncols + col) =
                    *reinterpret_cast<uint32_t*>(&hp0);
                *reinterpret_cast<uint32_t*>(Chi + (size_t)(r0 + 8) * Ncols + col) =
                    *reinterpret_cast<uint32_t*>(&hp1);
                if (MODE == 1) {
                    const __half l00 = __float2half_rn(v00 - __half2float(h00));
                    const __half l01 = __float2half_rn(v01 - __half2float(h01));
                    const __half l10 = __float2half_rn(v10 - __half2float(h10));
                    const __half l11 = __float2half_rn(v11 - __half2float(h11));
                    __half2 lp0 = __halves2half2(l00, l01);
                    __half2 lp1 = __halves2half2(l10, l11);
                    *reinterpret_cast<uint32_t*>(Clo + (size_t)r0 * Ncols + col) =
                        *reinterpret_cast<uint32_t*>(&lp0);
                    *reinterpret_cast<uint32_t*>(Clo + (size_t)(r0 + 8) * Ncols + col) =
                        *reinterpret_cast<uint32_t*>(&lp1);
                }
            }
            if (MODE == 1) {
                atomicAdd(&sq_s[r0 - mBase], ss0);
                atomicAdd(&sq_s[r0 + 8 - mBase], ss1);
            }
        }
        if (MODE == 1) {
            __syncthreads();
            if (tid < 128) Cf[mBase + tid] = sq_s[tid];
        }
    }
}

static const int SMEM_M0 = 3 * 40960 + 512;   // 123392
static const int SMEM_M1 = 4 * 24576 + 512;   // 98816
static const int SMEM_M2 = 3 * 32768 + 512;   // 98816

// ---------------- conversion kernels ----------------
__global__ void split_hi_kernel(const float* __restrict__ x,
                                __half* __restrict__ hi, int n4) {
    int i = blockIdx.x * 256 + threadIdx.x;
    if (i >= n4) return;
    float4 v = reinterpret_cast<const float4*>(x)[i];
    __half2 h0 = __halves2half2(__float2half_rn(v.x), __float2half_rn(v.y));
    __half2 h1 = __halves2half2(__float2half_rn(v.z), __float2half_rn(v.w));
    reinterpret_cast<uint2*>(hi)[i] =
        make_uint2(*reinterpret_cast<uint32_t*>(&h0), *reinterpret_cast<uint32_t*>(&h1));
}

__global__ void transpose_split_kernel(const float* __restrict__ W,
                                       __half* __restrict__ th,
                                       __half* __restrict__ tl, int K, int N) {
    __shared__ float tile[32][33];
    const int kb = blockIdx.y * 32;
    const int nb = blockIdx.x * 32;
    const int tx = threadIdx.x, ty = threadIdx.y;   // block (32, 8)
#pragma unroll
    for (int i = 0; i < 4; ++i)
        tile[ty + i * 8][tx] = W[(size_t)(kb + ty + i * 8) * N + nb + tx];
    __syncthreads();
#pragma unroll
    for (int i = 0; i < 4; ++i) {
        const int n = nb + ty + i * 8;
        const int k = kb + tx;
        const float v = tile[tx][ty + i * 8];
        const __half h = __float2half_rn(v);
        th[(size_t)n * K + k] = h;
        tl[(size_t)n * K + k] = __float2half_rn(v - __half2float(h));
    }
}

// ---------------------------------------------------------------------------
extern "C" void kernel_launch(void* const* d_in, const int* in_sizes, int n_in,
                              void* d_out, int out_size) {
    const float* batch = (const float*)d_in[0];
    const float* W1    = (const float*)d_in[1];
    const float* b1    = (const float*)d_in[2];
    const float* W2    = (const float*)d_in[3];
    const float* b2    = (const float*)d_in[4];
    float* out = (float*)d_out;

    __half *a_hi, *h_hi, *w1t_hi, *w1t_lo, *w2t_hi, *w2t_lo, *t_hi, *t_lo;
    float *sq_ptr;
    cudaGetSymbolAddress((void**)&a_hi,   g_a_hi);
    cudaGetSymbolAddress((void**)&h_hi,   g_h_hi);
    cudaGetSymbolAddress((void**)&w1t_hi, g_w1t_hi);
    cudaGetSymbolAddress((void**)&w1t_lo, g_w1t_lo);
    cudaGetSymbolAddress((void**)&w2t_hi, g_w2t_hi);
    cudaGetSymbolAddress((void**)&w2t_lo, g_w2t_lo);
    cudaGetSymbolAddress((void**)&t_hi,   g_t_hi);
    cudaGetSymbolAddress((void**)&t_lo,   g_t_lo);
    cudaGetSymbolAddress((void**)&sq_ptr, g_sq);

    cudaFuncSetAttribute(mma_gemm<0>, cudaFuncAttributeMaxDynamicSharedMemorySize, SMEM_M0);
    cudaFuncSetAttribute(mma_gemm<1>, cudaFuncAttributeMaxDynamicSharedMemorySize, SMEM_M1);
    cudaFuncSetAttribute(mma_gemm<2>, cudaFuncAttributeMaxDynamicSharedMemorySize, SMEM_M2);

    // 0) precision splits
    {
        int n4 = M_TOT * D_DIM / 4;
        split_hi_kernel<<<(n4 + 255) / 256, 256>>>(batch, a_hi, n4);
        transpose_split_kernel<<<dim3(H_DIM / 32, D_DIM / 32), dim3(32, 8)>>>(
            W1, w1t_hi, w1t_lo, D_DIM, H_DIM);
        transpose_split_kernel<<<dim3(R_DIM / 32, H_DIM / 32), dim3(32, 8)>>>(
            W2, w2t_hi, w2t_lo, H_DIM, R_DIM);
    }
    // 1) h = relu(batch @ W1 + b1) -> half hi   (CTA tile 128x256)
    {
        dim3 grid(H_DIM / 256, M_TOT / 128);   // (4, 128)
        mma_gemm<0><<<grid, 256, SMEM_M0>>>(
            a_hi, nullptr, w1t_hi, w1t_lo, b1, nullptr, h_hi, nullptr, D_DIM, H_DIM);
    }
    // 2) t = relu(h @ W2 + b2) -> half hi/lo + per-row squared norms
    {
        dim3 grid(R_DIM / 128, M_TOT / 128);   // (1, 128)
        mma_gemm<1><<<grid, 256, SMEM_M1>>>(
            h_hi, nullptr, w2t_hi, w2t_lo, b2, sq_ptr, t_hi, t_lo, H_DIM, R_DIM);
    }
    // 3) pairwise distances: out[b,i,j] = max(sq_i + sq_j - 2 t_i.t_j, 0)
    {
        dim3 grid(L_DIM / 128, L_DIM / 128, B_DIM);   // (8, 8, 16)
        mma_gemm<2><<<grid, 256, SMEM_M2>>>(
            t_hi, t_lo, t_hi, t_lo, sq_ptr, out, nullptr, nullptr, R_DIM, L_DIM);
    }
}

// round 8
// speedup vs baseline: 1.1764x; 1.1764x over previous
#include <cuda_runtime.h>
#include <cuda_fp16.h>
#include <cstdint>
#include <cstddef>

// Shapes: batch[16,1024,1024] -> M=16384,K=1024 ; W1[1024,1024] ; W2[1024,128]
// out[16,1024,1024] fp32.
static const int M_TOT = 16384;
static const int D_DIM = 1024;
static const int H_DIM = 1024;
static const int R_DIM = 128;
static const int L_DIM = 1024;
static const int B_DIM = 16;

// ---- scratch (__device__ globals; no runtime allocation allowed) ----
__device__ __align__(256) __half g_a_hi[(size_t)16384 * 1024];
__device__ __align__(256) __half g_h_hi[(size_t)16384 * 1024];
__device__ __align__(256) __half g_w1t_hi[(size_t)1024 * 1024];
__device__ __align__(256) __half g_w1t_lo[(size_t)1024 * 1024];
__device__ __align__(256) __half g_w2t_hi[(size_t)128 * 1024];
__device__ __align__(256) __half g_w2t_lo[(size_t)128 * 1024];
__device__ __align__(256) __half g_t_hi[(size_t)16384 * 128];
__device__ __align__(256) __half g_t_lo[(size_t)16384 * 128];
__device__ __align__(256) float g_sq[16384];

// ---------------- PTX helpers ----------------
__device__ __forceinline__ uint32_t smem_u32(const void* p) {
    uint32_t a;
    asm("{ .reg .u64 t; cvta.to.shared.u64 t, %1; cvt.u32.u64 %0, t; }" : "=r"(a) : "l"(p));
    return a;
}
__device__ __forceinline__ void cp16(uint32_t saddr, const void* g) {
    asm volatile("cp.async.cg.shared.global [%0], [%1], 16;" :: "r"(saddr), "l"(g));
}
__device__ __forceinline__ void cp_commit() {
    asm volatile("cp.async.commit_group;" ::: "memory");
}
__device__ __forceinline__ void ldsm4(uint32_t* r, uint32_t addr) {
    asm volatile("ldmatrix.sync.aligned.m8n8.x4.shared.b16 {%0,%1,%2,%3}, [%4];"
                 : "=r"(r[0]), "=r"(r[1]), "=r"(r[2]), "=r"(r[3]) : "r"(addr));
}
__device__ __forceinline__ void mma_f16(float* c, const uint32_t* a, const uint32_t* b) {
    asm volatile(
        "mma.sync.aligned.m16n8k16.row.col.f32.f16.f16.f32 "
        "{%0,%1,%2,%3}, {%4,%5,%6,%7}, {%8,%9}, {%0,%1,%2,%3};"
        : "+f"(c[0]), "+f"(c[1]), "+f"(c[2]), "+f"(c[3])
        : "r"(a[0]), "r"(a[1]), "r"(a[2]), "r"(a[3]), "r"(b[0]), "r"(b[1]));
}

// ---------------- unified tensor-core GEMM ------------------------
// acc = A @ B^T, fp16 split operands, fp32 accumulate.
// MODE 0 (GEMM1): 2 products (Ah*Bh + Ah*Bl); C = relu(acc+bias) -> half hi only
// MODE 1 (GEMM2): 2 products; C -> half hi/lo + per-row sumsq -> Cf(=g_sq)
// MODE 2 (DIST):  3 products (+Al*Bh); out = max(sq_i+sq_j-2*acc, 0); bias = sq
// CTA tile 128x128, BK=32. 8 warps as 2(m) x 4(n); warp tile 64x32.
// smem rows are 64B; 16B chunk sub of row r stored at sub'=(sub+(r>>1))&3.
template <int MODE>
__global__ __launch_bounds__(256, 2)
void mma_gemm(const __half* __restrict__ Ahi, const __half* __restrict__ Alo,
              const __half* __restrict__ Bhi, const __half* __restrict__ Blo,
              const float* __restrict__ bias,
              float* __restrict__ Cf,
              __half* __restrict__ Chi, __half* __restrict__ Clo,
              int K, int Ncols) {
    constexpr int NSTG = (MODE == 2) ? 3 : 4;
    constexpr int ASZ  = (MODE == 2) ? 16384 : 8192;
    constexpr int STG  = ASZ + 16384;
    constexpr int NITER = STG / 16 / 256;          // 6 or 8
    constexpr bool PROD3 = (MODE == 2);

    extern __shared__ char smem[];
    const uint32_t sbase = smem_u32(smem);
    float* sq_s = reinterpret_cast<float*>(smem + NSTG * STG);
    const int tid = threadIdx.x;
    const int lane = tid & 31;
    const int wid = tid >> 5;
    const int warp_m = wid & 1;       // 2 m-warps
    const int warp_n = wid >> 1;      // 4 n-warps

    const int mBase = blockIdx.y * 128;
    const int nBase = blockIdx.x * 128;
    const int zb = (MODE == 2) ? blockIdx.z : 0;
    const size_t zrow = (size_t)zb * 1024;
    const int NC = K >> 5;

    if (MODE == 1 && tid < 128) sq_s[tid] = 0.0f;

    float acc[4][4][4];
#pragma unroll
    for (int i = 0; i < 4; i++)
#pragma unroll
        for (int j = 0; j < 4; j++)
#pragma unroll
            for (int q = 0; q < 4; q++) acc[i][j][q] = 0.0f;

    auto load_chunk = [&](int c, int stg) {
        const int k0 = c << 5;
        const uint32_t sb = sbase + stg * STG;
#pragma unroll
        for (int it = 0; it < NITER; ++it) {
            const int seg = it >> 1;
            const int l = (tid + it * 256) & 511;
            const int row = l >> 2;
            const int sub = l & 3;
            const __half* src;
            uint32_t soff;
            int rb;
            if (MODE == 2) {
                src = (seg == 0) ? Ahi : (seg == 1) ? Alo : (seg == 2) ? Bhi : Blo;
                soff = (uint32_t)seg * 8192u;
                rb = (seg < 2) ? mBase : nBase;
            } else {
                src = (seg == 0) ? Ahi : (seg == 1) ? Bhi : Blo;
                soff = (seg == 0) ? 0u : (seg == 1) ? (uint32_t)ASZ : (uint32_t)ASZ + 8192u;
                rb = (seg == 0) ? mBase : nBase;
            }
            const size_t goff = (zrow + rb + row) * (size_t)K + k0 + sub * 8;
            const uint32_t dst = sb + soff + row * 64 + (((sub + (row >> 1)) & 3) << 4);
            cp16(dst, src + goff);
        }
    };

    load_chunk(0, 0); cp_commit();
#pragma unroll
    for (int s = 1; s < NSTG; ++s) {
        if (s < NC) load_chunk(s, s);
        cp_commit();
    }

    // ldmatrix per-lane components (swizzle base is fragment-invariant)
    const int a_row_l = lane & 15;
    const int a_sw = (lane >> 4) + (a_row_l >> 1);
    const int b_row_l = (lane & 7) + ((lane >> 4) << 3);
    const int b_sw = ((lane >> 3) & 1) + (b_row_l >> 1);

    for (int c = 0; c < NC; ++c) {
        if constexpr (NSTG == 4) asm volatile("cp.async.wait_group 2;" ::: "memory");
        else                     asm volatile("cp.async.wait_group 1;" ::: "memory");
        __syncthreads();
        const uint32_t base = sbase + (c % NSTG) * STG;
#pragma unroll
        for (int ks = 0; ks < 2; ++ks) {
            // A fragments for this ks first ...
            uint32_t Ah[4][4], Al[4][4];
#pragma unroll
            for (int mi = 0; mi < 4; ++mi) {
                const int row = warp_m * 64 + mi * 16 + a_row_l;
                const uint32_t addr = base + row * 64 + (((ks * 2 + a_sw) & 3) << 4);
                ldsm4(Ah[mi], addr);
                if (PROD3) ldsm4(Al[mi], addr + 8192);
            }
            // ... then the prefetch burst overlaps ldsm latency (once per chunk)
            if (ks == 0) {
                if (c + NSTG - 1 < NC) load_chunk(c + NSTG - 1, (c + NSTG - 1) % NSTG);
                cp_commit();
            }
#pragma unroll
            for (int np = 0; np < 2; ++np) {
                uint32_t Bh[4], Bl[4];
                const int n = warp_n * 32 + np * 16 + b_row_l;
                const uint32_t baddr = base + ASZ + n * 64 + (((ks * 2 + b_sw) & 3) << 4);
                ldsm4(Bh, baddr);
                ldsm4(Bl, baddr + 8192);
#pragma unroll
                for (int half = 0; half < 2; ++half) {
                    const uint32_t bh[2] = {Bh[half * 2], Bh[half * 2 + 1]};
                    const uint32_t bl[2] = {Bl[half * 2], Bl[half * 2 + 1]};
#pragma unroll
                    for (int mi = 0; mi < 4; ++mi)
                        mma_f16(acc[mi][np * 2 + half], Ah[mi], bh);
#pragma unroll
                    for (int mi = 0; mi < 4; ++mi)
                        mma_f16(acc[mi][np * 2 + half], Ah[mi], bl);
                    if (PROD3) {
#pragma unroll
                        for (int mi = 0; mi < 4; ++mi)
                            mma_f16(acc[mi][np * 2 + half], Al[mi], bh);
                    }
                }
            }
        }
    }

    // ---------------- epilogue ----------------
    if (MODE == 2) {
        const float* sqg = bias + zb * 1024;
        float* Ob = Cf + (size_t)zb * 1024 * 1024;
#pragma unroll
        for (int mi = 0; mi < 4; ++mi) {
            const int r0 = mBase + warp_m * 64 + mi * 16 + (lane >> 2);
            const float sr0 = sqg[r0], sr1 = sqg[r0 + 8];
#pragma unroll
            for (int ni = 0; ni < 4; ++ni) {
                const int col = nBase + warp_n * 32 + ni * 8 + 2 * (lane & 3);
                const float sc0 = sqg[col], sc1 = sqg[col + 1];
                const float* cc = acc[mi][ni];
                *reinterpret_cast<float2*>(Ob + (size_t)r0 * Ncols + col) =
                    make_float2(fmaxf(sr0 + sc0 - 2.0f * cc[0], 0.f),
                                fmaxf(sr0 + sc1 - 2.0f * cc[1], 0.f));
                *reinterpret_cast<float2*>(Ob + (size_t)(r0 + 8) * Ncols + col) =
                    make_float2(fmaxf(sr1 + sc0 - 2.0f * cc[2], 0.f),
                                fmaxf(sr1 + sc1 - 2.0f * cc[3], 0.f));
            }
        }
    } else {
#pragma unroll
        for (int mi = 0; mi < 4; ++mi) {
            const int r0 = mBase + warp_m * 64 + mi * 16 + (lane >> 2);
            float ss0 = 0.0f, ss1 = 0.0f;
#pragma unroll
            for (int ni = 0; ni < 4; ++ni) {
                const int col = nBase + warp_n * 32 + ni * 8 + 2 * (lane & 3);
                const float bz0 = __ldg(&bias[col]), bz1 = __ldg(&bias[col + 1]);
                const float* cc = acc[mi][ni];
                const float v00 = fmaxf(cc[0] + bz0, 0.f), v01 = fmaxf(cc[1] + bz1, 0.f);
                const float v10 = fmaxf(cc[2] + bz0, 0.f), v11 = fmaxf(cc[3] + bz1, 0.f);
                if (MODE == 1) { ss0 += v00 * v00 + v01 * v01; ss1 += v10 * v10 + v11 * v11; }
                const __half h00 = __float2half_rn(v00), h01 = __float2half_rn(v01);
                const __half h10 = __float2half_rn(v10), h11 = __float2half_rn(v11);
                __half2 hp0 = __halves2half2(h00, h01);
                __half2 hp1 = __halves2half2(h10, h11);
                *reinterpret_cast<uint32_t*>(Chi + (size_t)r0 * Ncols + col) =
                    *reinterpret_cast<uint32_t*>(&hp0);
                *reinterpret_cast<uint32_t*>(Chi + (size_t)(r0 + 8) * Ncols + col) =
                    *reinterpret_cast<uint32_t*>(&hp1);
                if (MODE == 1) {
                    const __half l00 = __float2half_rn(v00 - __half2float(h00));
                    const __half l01 = __float2half_rn(v01 - __half2float(h01));
                    const __half l10 = __float2half_rn(v10 - __half2float(h10));
                    const __half l11 = __float2half_rn(v11 - __half2float(h11));
                    __half2 lp0 = __halves2half2(l00, l01);
                    __half2 lp1 = __halves2half2(l10, l11);
                    *reinterpret_cast<uint32_t*>(Clo + (size_t)r0 * Ncols + col) =
                        *reinterpret_cast<uint32_t*>(&lp0);
                    *reinterpret_cast<uint32_t*>(Clo + (size_t)(r0 + 8) * Ncols + col) =
                        *reinterpret_cast<uint32_t*>(&lp1);
                }
            }
            if (MODE == 1) {
                atomicAdd(&sq_s[r0 - mBase], ss0);
                atomicAdd(&sq_s[r0 + 8 - mBase], ss1);
            }
        }
        if (MODE == 1) {
            __syncthreads();
            if (tid < 128) Cf[mBase + tid] = sq_s[tid];
        }
    }
}

static const int SMEM_M01 = 4 * 24576 + 512;   // 98816
static const int SMEM_M2  = 3 * 32768 + 512;   // 98816

// ---------------- fused conversion kernel ----------------
// blocks [0, 16384): batch fp32 -> a_hi fp16 (float4-strided)
// blocks [16384, 17408): W1 transpose-split 32x32 tiles
// blocks [17408, 17536): W2 transpose-split 32x32 tiles
__global__ void prep_kernel(const float* __restrict__ batch,
                            const float* __restrict__ W1,
                            const float* __restrict__ W2,
                            __half* __restrict__ a_hi,
                            __half* __restrict__ w1t_hi, __half* __restrict__ w1t_lo,
                            __half* __restrict__ w2t_hi, __half* __restrict__ w2t_lo) {
    __shared__ float tile[32][33];
    const int b = blockIdx.x;
    const int tid = threadIdx.x;
    if (b < 16384) {
        const int i = b * 256 + tid;
        float4 v = reinterpret_cast<const float4*>(batch)[i];
        __half2 h0 = __halves2half2(__float2half_rn(v.x), __float2half_rn(v.y));
        __half2 h1 = __halves2half2(__float2half_rn(v.z), __float2half_rn(v.w));
        reinterpret_cast<uint2*>(a_hi)[i] =
            make_uint2(*reinterpret_cast<uint32_t*>(&h0), *reinterpret_cast<uint32_t*>(&h1));
        return;
    }
    const bool isW1 = (b < 16384 + 1024);
    const int idx = isW1 ? (b - 16384) : (b - 16384 - 1024);
    const int ncols = isW1 ? 1024 : 128;         // N of W
    const int ntiles = ncols / 32;
    const int nb = (idx % ntiles) * 32;
    const int kb = (idx / ntiles) * 32;
    const float* W = isW1 ? W1 : W2;
    __half* th = isW1 ? w1t_hi : w2t_hi;
    __half* tl = isW1 ? w1t_lo : w2t_lo;
    const int K = 1024;
    const int tx = tid & 31, ty = tid >> 5;      // (32, 8)
#pragma unroll
    for (int i = 0; i < 4; ++i)
        tile[ty + i * 8][tx] = W[(size_t)(kb + ty + i * 8) * ncols + nb + tx];
    __syncthreads();
#pragma unroll
    for (int i = 0; i < 4; ++i) {
        const int n = nb + ty + i * 8;
        const int k = kb + tx;
        const float v = tile[tx][ty + i * 8];
        const __half h = __float2half_rn(v);
        th[(size_t)n * K + k] = h;
        tl[(size_t)n * K + k] = __float2half_rn(v - __half2float(h));
    }
}

// ---------------------------------------------------------------------------
extern "C" void kernel_launch(void* const* d_in, const int* in_sizes, int n_in,
                              void* d_out, int out_size) {
    const float* batch = (const float*)d_in[0];
    const float* W1    = (const float*)d_in[1];
    const float* b1    = (const float*)d_in[2];
    const float* W2    = (const float*)d_in[3];
    const float* b2    = (const float*)d_in[4];
    float* out = (float*)d_out;

    __half *a_hi, *h_hi, *w1t_hi, *w1t_lo, *w2t_hi, *w2t_lo, *t_hi, *t_lo;
    float *sq_ptr;
    cudaGetSymbolAddress((void**)&a_hi,   g_a_hi);
    cudaGetSymbolAddress((void**)&h_hi,   g_h_hi);
    cudaGetSymbolAddress((void**)&w1t_hi, g_w1t_hi);
    cudaGetSymbolAddress((void**)&w1t_lo, g_w1t_lo);
    cudaGetSymbolAddress((void**)&w2t_hi, g_w2t_hi);
    cudaGetSymbolAddress((void**)&w2t_lo, g_w2t_lo);
    cudaGetSymbolAddress((void**)&t_hi,   g_t_hi);
    cudaGetSymbolAddress((void**)&t_lo,   g_t_lo);
    cudaGetSymbolAddress((void**)&sq_ptr, g_sq);

    cudaFuncSetAttribute(mma_gemm<0>, cudaFuncAttributeMaxDynamicSharedMemorySize, SMEM_M01);
    cudaFuncSetAttribute(mma_gemm<1>, cudaFuncAttributeMaxDynamicSharedMemorySize, SMEM_M01);
    cudaFuncSetAttribute(mma_gemm<2>, cudaFuncAttributeMaxDynamicSharedMemorySize, SMEM_M2);

    // 0) fused precision splits (batch -> hi; W1, W2 -> transposed hi/lo)
    prep_kernel<<<16384 + 1024 + 128, 256>>>(batch, W1, W2, a_hi,
                                             w1t_hi, w1t_lo, w2t_hi, w2t_lo);
    // 1) h = relu(batch @ W1 + b1) -> half hi
    {
        dim3 grid(H_DIM / 128, M_TOT / 128);   // (8, 128)
        mma_gemm<0><<<grid, 256, SMEM_M01>>>(
            a_hi, nullptr, w1t_hi, w1t_lo, b1, nullptr, h_hi, nullptr, D_DIM, H_DIM);
    }
    // 2) t = relu(h @ W2 + b2) -> half hi/lo + per-row squared norms
    {
        dim3 grid(R_DIM / 128, M_TOT / 128);   // (1, 128)
        mma_gemm<1><<<grid, 256, SMEM_M01>>>(
            h_hi, nullptr, w2t_hi, w2t_lo, b2, sq_ptr, t_hi, t_lo, H_DIM, R_DIM);
    }
    // 3) pairwise distances: out[b,i,j] = max(sq_i + sq_j - 2 t_i.t_j, 0)
    {
        dim3 grid(L_DIM / 128, L_DIM / 128, B_DIM);   // (8, 8, 16)
        mma_gemm<2><<<grid, 256, SMEM_M2>>>(
            t_hi, t_lo, t_hi, t_lo, sq_ptr, out, nullptr, nullptr, R_DIM, L_DIM);
    }
}

// round 9
// speedup vs baseline: 1.5234x; 1.2950x over previous
#include <cuda_runtime.h>
#include <cuda_fp16.h>
#include <cstdint>
#include <cstddef>

// Shapes: batch[16,1024,1024] -> M=16384,K=1024 ; W1[1024,1024] ; W2[1024,128]
// out[16,1024,1024] fp32.
static const int M_TOT = 16384;
static const int D_DIM = 1024;
static const int H_DIM = 1024;
static const int R_DIM = 128;
static const int L_DIM = 1024;
static const int B_DIM = 16;

// ---- scratch (__device__ globals; no runtime allocation allowed) ----
__device__ __align__(256) __half g_a_hi[(size_t)16384 * 1024];
__device__ __align__(256) __half g_h_hi[(size_t)16384 * 1024];
__device__ __align__(256) __half g_w1t_hi[(size_t)1024 * 1024];
__device__ __align__(256) __half g_w2t_hi[(size_t)128 * 1024];
__device__ __align__(256) __half g_w2t_lo[(size_t)128 * 1024];
__device__ __align__(256) __half g_t_hi[(size_t)16384 * 128];
__device__ __align__(256) __half g_t_lo[(size_t)16384 * 128];
__device__ __align__(256) float g_sq[16384];

// ---------------- PTX helpers ----------------
__device__ __forceinline__ uint32_t smem_u32(const void* p) {
    uint32_t a;
    asm("{ .reg .u64 t; cvta.to.shared.u64 t, %1; cvt.u32.u64 %0, t; }" : "=r"(a) : "l"(p));
    return a;
}
__device__ __forceinline__ void cp16(uint32_t saddr, const void* g) {
    asm volatile("cp.async.cg.shared.global [%0], [%1], 16;" :: "r"(saddr), "l"(g));
}
__device__ __forceinline__ void cp_commit() {
    asm volatile("cp.async.commit_group;" ::: "memory");
}
__device__ __forceinline__ void ldsm4(uint32_t* r, uint32_t addr) {
    asm volatile("ldmatrix.sync.aligned.m8n8.x4.shared.b16 {%0,%1,%2,%3}, [%4];"
                 : "=r"(r[0]), "=r"(r[1]), "=r"(r[2]), "=r"(r[3]) : "r"(addr));
}
__device__ __forceinline__ void mma_f16(float* c, const uint32_t* a, const uint32_t* b) {
    asm volatile(
        "mma.sync.aligned.m16n8k16.row.col.f32.f16.f16.f32 "
        "{%0,%1,%2,%3}, {%4,%5,%6,%7}, {%8,%9}, {%0,%1,%2,%3};"
        : "+f"(c[0]), "+f"(c[1]), "+f"(c[2]), "+f"(c[3])
        : "r"(a[0]), "r"(a[1]), "r"(a[2]), "r"(a[3]), "r"(b[0]), "r"(b[1]));
}

// ---------------- unified tensor-core GEMM ------------------------
// acc = A @ B^T, fp16 operands, fp32 accumulate.
// MODE 0 (GEMM1): 1 product (Ah*Bh);            C = relu(acc+bias) -> half hi
// MODE 1 (GEMM2): 2 products (Ah*Bh + Ah*Bl);   C -> hi/lo + row sumsq -> Cf
// MODE 2 (DIST):  3 products (+Al*Bh);          out = max(sq_i+sq_j-2*acc,0)
// CTA tile 128x128, BK=32. 8 warps as 2(m) x 4(n); warp tile 64x32.
// smem rows are 64B; 16B chunk sub of row r stored at sub'=(sub+(r>>1))&3.
template <int MODE>
__global__ __launch_bounds__(256, 2)
void mma_gemm(const __half* __restrict__ Ahi, const __half* __restrict__ Alo,
              const __half* __restrict__ Bhi, const __half* __restrict__ Blo,
              const float* __restrict__ bias,
              float* __restrict__ Cf,
              __half* __restrict__ Chi, __half* __restrict__ Clo,
              int K, int Ncols) {
    constexpr int NPROD = (MODE == 0) ? 1 : (MODE == 1) ? 2 : 3;
    constexpr int ASZ  = (NPROD == 3) ? 16384 : 8192;
    constexpr int BSZ  = (NPROD >= 2) ? 16384 : 8192;
    constexpr int STG  = ASZ + BSZ;                 // 16K / 24K / 32K
    constexpr int NSTG = (MODE == 0) ? 6 : (MODE == 1) ? 4 : 3;
    constexpr int NITER = STG / 16 / 256;           // 4 / 6 / 8

    extern __shared__ char smem[];
    const uint32_t sbase = smem_u32(smem);
    float* sq_s = reinterpret_cast<float*>(smem + NSTG * STG);
    const int tid = threadIdx.x;
    const int lane = tid & 31;
    const int wid = tid >> 5;
    const int warp_m = wid & 1;       // 2 m-warps
    const int warp_n = wid >> 1;      // 4 n-warps

    const int mBase = blockIdx.y * 128;
    const int nBase = blockIdx.x * 128;
    const int zb = (MODE == 2) ? blockIdx.z : 0;
    const size_t zrow = (size_t)zb * 1024;
    const int NC = K >> 5;

    if (MODE == 1 && tid < 128) sq_s[tid] = 0.0f;

    float acc[4][4][4];
#pragma unroll
    for (int i = 0; i < 4; i++)
#pragma unroll
        for (int j = 0; j < 4; j++)
#pragma unroll
            for (int q = 0; q < 4; q++) acc[i][j][q] = 0.0f;

    auto load_chunk = [&](int c, int stg) {
        const int k0 = c << 5;
        const uint32_t sb = sbase + stg * STG;
#pragma unroll
        for (int it = 0; it < NITER; ++it) {
            const int seg = it >> 1;
            const int l = (tid + it * 256) & 511;
            const int row = l >> 2;
            const int sub = l & 3;
            const __half* src;
            uint32_t soff;
            int rb;
            if (MODE == 0) {
                // segs: 0=A-hi 1=B-hi
                src = (seg == 0) ? Ahi : Bhi;
                soff = (seg == 0) ? 0u : (uint32_t)ASZ;
                rb = (seg == 0) ? mBase : nBase;
            } else if (MODE == 1) {
                // segs: 0=A-hi 1=B-hi 2=B-lo
                src = (seg == 0) ? Ahi : (seg == 1) ? Bhi : Blo;
                soff = (seg == 0) ? 0u : (seg == 1) ? (uint32_t)ASZ : (uint32_t)ASZ + 8192u;
                rb = (seg == 0) ? mBase : nBase;
            } else {
                // segs: 0=A-hi 1=A-lo 2=B-hi 3=B-lo
                src = (seg == 0) ? Ahi : (seg == 1) ? Alo : (seg == 2) ? Bhi : Blo;
                soff = (uint32_t)seg * 8192u;
                rb = (seg < 2) ? mBase : nBase;
            }
            const size_t goff = (zrow + rb + row) * (size_t)K + k0 + sub * 8;
            const uint32_t dst = sb + soff + row * 64 + (((sub + (row >> 1)) & 3) << 4);
            cp16(dst, src + goff);
        }
    };

    load_chunk(0, 0); cp_commit();
#pragma unroll
    for (int s = 1; s < NSTG; ++s) {
        if (s < NC) load_chunk(s, s);
        cp_commit();
    }

    // ldmatrix per-lane components (swizzle base is fragment-invariant)
    const int a_row_l = lane & 15;
    const int a_sw = (lane >> 4) + (a_row_l >> 1);
    const int b_row_l = (lane & 7) + ((lane >> 4) << 3);
    const int b_sw = ((lane >> 3) & 1) + (b_row_l >> 1);

    for (int c = 0; c < NC; ++c) {
        asm volatile("cp.async.wait_group %0;" :: "n"(NSTG - 2) : "memory");
        __syncthreads();
        const uint32_t base = sbase + (c % NSTG) * STG;
#pragma unroll
        for (int ks = 0; ks < 2; ++ks) {
            uint32_t Ah[4][4], Al[4][4];
#pragma unroll
            for (int mi = 0; mi < 4; ++mi) {
                const int row = warp_m * 64 + mi * 16 + a_row_l;
                const uint32_t addr = base + row * 64 + (((ks * 2 + a_sw) & 3) << 4);
                ldsm4(Ah[mi], addr);
                if (NPROD == 3) ldsm4(Al[mi], addr + 8192);
            }
            if (ks == 0) {
                if (c + NSTG - 1 < NC) load_chunk(c + NSTG - 1, (c + NSTG - 1) % NSTG);
                cp_commit();
            }
#pragma unroll
            for (int np = 0; np < 2; ++np) {
                uint32_t Bh[4], Bl[4];
                const int n = warp_n * 32 + np * 16 + b_row_l;
                const uint32_t baddr = base + ASZ + n * 64 + (((ks * 2 + b_sw) & 3) << 4);
                ldsm4(Bh, baddr);
                if (NPROD >= 2) ldsm4(Bl, baddr + 8192);
#pragma unroll
                for (int half = 0; half < 2; ++half) {
                    const uint32_t bh[2] = {Bh[half * 2], Bh[half * 2 + 1]};
#pragma unroll
                    for (int mi = 0; mi < 4; ++mi)
                        mma_f16(acc[mi][np * 2 + half], Ah[mi], bh);
                    if (NPROD >= 2) {
                        const uint32_t bl[2] = {Bl[half * 2], Bl[half * 2 + 1]};
#pragma unroll
                        for (int mi = 0; mi < 4; ++mi)
                            mma_f16(acc[mi][np * 2 + half], Ah[mi], bl);
                    }
                    if (NPROD == 3) {
#pragma unroll
                        for (int mi = 0; mi < 4; ++mi)
                            mma_f16(acc[mi][np * 2 + half], Al[mi], bh);
                    }
                }
            }
        }
    }

    // ---------------- epilogue ----------------
    if (MODE == 2) {
        const float* sqg = bias + zb * 1024;
        float* Ob = Cf + (size_t)zb * 1024 * 1024;
#pragma unroll
        for (int mi = 0; mi < 4; ++mi) {
            const int r0 = mBase + warp_m * 64 + mi * 16 + (lane >> 2);
            const float sr0 = sqg[r0], sr1 = sqg[r0 + 8];
#pragma unroll
            for (int ni = 0; ni < 4; ++ni) {
                const int col = nBase + warp_n * 32 + ni * 8 + 2 * (lane & 3);
                const float sc0 = sqg[col], sc1 = sqg[col + 1];
                const float* cc = acc[mi][ni];
                *reinterpret_cast<float2*>(Ob + (size_t)r0 * Ncols + col) =
                    make_float2(fmaxf(sr0 + sc0 - 2.0f * cc[0], 0.f),
                                fmaxf(sr0 + sc1 - 2.0f * cc[1], 0.f));
                *reinterpret_cast<float2*>(Ob + (size_t)(r0 + 8) * Ncols + col) =
                    make_float2(fmaxf(sr1 + sc0 - 2.0f * cc[2], 0.f),
                                fmaxf(sr1 + sc1 - 2.0f * cc[3], 0.f));
            }
        }
    } else {
#pragma unroll
        for (int mi = 0; mi < 4; ++mi) {
            const int r0 = mBase + warp_m * 64 + mi * 16 + (lane >> 2);
            float ss0 = 0.0f, ss1 = 0.0f;
#pragma unroll
            for (int ni = 0; ni < 4; ++ni) {
                const int col = nBase + warp_n * 32 + ni * 8 + 2 * (lane & 3);
                const float bz0 = __ldg(&bias[col]), bz1 = __ldg(&bias[col + 1]);
                const float* cc = acc[mi][ni];
                const float v00 = fmaxf(cc[0] + bz0, 0.f), v01 = fmaxf(cc[1] + bz1, 0.f);
                const float v10 = fmaxf(cc[2] + bz0, 0.f), v11 = fmaxf(cc[3] + bz1, 0.f);
                if (MODE == 1) { ss0 += v00 * v00 + v01 * v01; ss1 += v10 * v10 + v11 * v11; }
                const __half h00 = __float2half_rn(v00), h01 = __float2half_rn(v01);
                const __half h10 = __float2half_rn(v10), h11 = __float2half_rn(v11);
                __half2 hp0 = __halves2half2(h00, h01);
                __half2 hp1 = __halves2half2(h10, h11);
                *reinterpret_cast<uint32_t*>(Chi + (size_t)r0 * Ncols + col) =
                    *reinterpret_cast<uint32_t*>(&hp0);
                *reinterpret_cast<uint32_t*>(Chi + (size_t)(r0 + 8) * Ncols + col) =
                    *reinterpret_cast<uint32_t*>(&hp1);
                if (MODE == 1) {
                    const __half l00 = __float2half_rn(v00 - __half2float(h00));
                    const __half l01 = __float2half_rn(v01 - __half2float(h01));
                    const __half l10 = __float2half_rn(v10 - __half2float(h10));
                    const __half l11 = __float2half_rn(v11 - __half2float(h11));
                    __half2 lp0 = __halves2half2(l00, l01);
                    __half2 lp1 = __halves2half2(l10, l11);
                    *reinterpret_cast<uint32_t*>(Clo + (size_t)r0 * Ncols + col) =
                        *reinterpret_cast<uint32_t*>(&lp0);
                    *reinterpret_cast<uint32_t*>(Clo + (size_t)(r0 + 8) * Ncols + col) =
                        *reinterpret_cast<uint32_t*>(&lp1);
                }
            }
            if (MODE == 1) {
                atomicAdd(&sq_s[r0 - mBase], ss0);
                atomicAdd(&sq_s[r0 + 8 - mBase], ss1);
            }
        }
        if (MODE == 1) {
            __syncthreads();
            if (tid < 128) Cf[mBase + tid] = sq_s[tid];
        }
    }
}

static const int SMEM_M0 = 6 * 16384 + 512;   // 98816
static const int SMEM_M1 = 4 * 24576 + 512;   // 98816
static const int SMEM_M2 = 3 * 32768 + 512;   // 98816

// ---------------- fused conversion kernel ----------------
// blocks [0, 16384): batch fp32 -> a_hi fp16
// blocks [16384, 17408): W1 transpose (hi only) 32x32 tiles
// blocks [17408, 17536): W2 transpose-split (hi/lo) 32x32 tiles
__global__ void prep_kernel(const float* __restrict__ batch,
                            const float* __restrict__ W1,
                            const float* __restrict__ W2,
                            __half* __restrict__ a_hi,
                            __half* __restrict__ w1t_hi,
                            __half* __restrict__ w2t_hi, __half* __restrict__ w2t_lo) {
    __shared__ float tile[32][33];
    const int b = blockIdx.x;
    const int tid = threadIdx.x;
    if (b < 16384) {
        const int i = b * 256 + tid;
        float4 v = reinterpret_cast<const float4*>(batch)[i];
        __half2 h0 = __halves2half2(__float2half_rn(v.x), __float2half_rn(v.y));
        __half2 h1 = __halves2half2(__float2half_rn(v.z), __float2half_rn(v.w));
        reinterpret_cast<uint2*>(a_hi)[i] =
            make_uint2(*reinterpret_cast<uint32_t*>(&h0), *reinterpret_cast<uint32_t*>(&h1));
        return;
    }
    const bool isW1 = (b < 16384 + 1024);
    const int idx = isW1 ? (b - 16384) : (b - 16384 - 1024);
    const int ncols = isW1 ? 1024 : 128;
    const int ntiles = ncols / 32;
    const int nb = (idx % ntiles) * 32;
    const int kb = (idx / ntiles) * 32;
    const float* W = isW1 ? W1 : W2;
    const int K = 1024;
    const int tx = tid & 31, ty = tid >> 5;   // (32, 8)
#pragma unroll
    for (int i = 0; i < 4; ++i)
        tile[ty + i * 8][tx] = W[(size_t)(kb + ty + i * 8) * ncols + nb + tx];
    __syncthreads();
#pragma unroll
    for (int i = 0; i < 4; ++i) {
        const int n = nb + ty + i * 8;
        const int k = kb + tx;
        const float v = tile[tx][ty + i * 8];
        const __half h = __float2half_rn(v);
        if (isW1) {
            w1t_hi[(size_t)n * K + k] = h;
        } else {
            w2t_hi[(size_t)n * K + k] = h;
            w2t_lo[(size_t)n * K + k] = __float2half_rn(v - __half2float(h));
        }
    }
}

// ---------------------------------------------------------------------------
extern "C" void kernel_launch(void* const* d_in, const int* in_sizes, int n_in,
                              void* d_out, int out_size) {
    const float* batch = (const float*)d_in[0];
    const float* W1    = (const float*)d_in[1];
    const float* b1    = (const float*)d_in[2];
    const float* W2    = (const float*)d_in[3];
    const float* b2    = (const float*)d_in[4];
    float* out = (float*)d_out;

    __half *a_hi, *h_hi, *w1t_hi, *w2t_hi, *w2t_lo, *t_hi, *t_lo;
    float *sq_ptr;
    cudaGetSymbolAddress((void**)&a_hi,   g_a_hi);
    cudaGetSymbolAddress((void**)&h_hi,   g_h_hi);
    cudaGetSymbolAddress((void**)&w1t_hi, g_w1t_hi);
    cudaGetSymbolAddress((void**)&w2t_hi, g_w2t_hi);
    cudaGetSymbolAddress((void**)&w2t_lo, g_w2t_lo);
    cudaGetSymbolAddress((void**)&t_hi,   g_t_hi);
    cudaGetSymbolAddress((void**)&t_lo,   g_t_lo);
    cudaGetSymbolAddress((void**)&sq_ptr, g_sq);

    cudaFuncSetAttribute(mma_gemm<0>, cudaFuncAttributeMaxDynamicSharedMemorySize, SMEM_M0);
    cudaFuncSetAttribute(mma_gemm<1>, cudaFuncAttributeMaxDynamicSharedMemorySize, SMEM_M1);
    cudaFuncSetAttribute(mma_gemm<2>, cudaFuncAttributeMaxDynamicSharedMemorySize, SMEM_M2);

    // 0) fused precision prep
    prep_kernel<<<16384 + 1024 + 128, 256>>>(batch, W1, W2, a_hi,
                                             w1t_hi, w2t_hi, w2t_lo);
    // 1) h = relu(batch @ W1 + b1) -> half hi   (single-product fp16)
    {
        dim3 grid(H_DIM / 128, M_TOT / 128);   // (8, 128)
        mma_gemm<0><<<grid, 256, SMEM_M0>>>(
            a_hi, nullptr, w1t_hi, nullptr, b1, nullptr, h_hi, nullptr, D_DIM, H_DIM);
    }
    // 2) t = relu(h @ W2 + b2) -> half hi/lo + per-row squared norms
    {
        dim3 grid(R_DIM / 128, M_TOT / 128);   // (1, 128)
        mma_gemm<1><<<grid, 256, SMEM_M1>>>(
            h_hi, nullptr, w2t_hi, w2t_lo, b2, sq_ptr, t_hi, t_lo, H_DIM, R_DIM);
    }
    // 3) pairwise distances: out[b,i,j] = max(sq_i + sq_j - 2 t_i.t_j, 0)
    {
        dim3 grid(L_DIM / 128, L_DIM / 128, B_DIM);   // (8, 8, 16)
        mma_gemm<2><<<grid, 256, SMEM_M2>>>(
            t_hi, t_lo, t_hi, t_lo, sq_ptr, out, nullptr, nullptr, R_DIM, L_DIM);
    }
}

// round 10
// speedup vs baseline: 1.7517x; 1.1498x over previous
#include <cuda_runtime.h>
#include <cuda_fp16.h>
#include <cstdint>
#include <cstddef>

// Shapes: batch[16,1024,1024] -> M=16384,K=1024 ; W1[1024,1024] ; W2[1024,128]
// out[16,1024,1024] fp32.
static const int M_TOT = 16384;
static const int D_DIM = 1024;
static const int H_DIM = 1024;
static const int R_DIM = 128;
static const int L_DIM = 1024;
static const int B_DIM = 16;

// ---- scratch (__device__ globals; no runtime allocation allowed) ----
__device__ __align__(256) __half g_a_hi[(size_t)16384 * 1024];
__device__ __align__(256) __half g_h_hi[(size_t)16384 * 1024];
__device__ __align__(256) __half g_w1t_hi[(size_t)1024 * 1024];
__device__ __align__(256) __half g_w2t_hi[(size_t)128 * 1024];
__device__ __align__(256) __half g_w2t_lo[(size_t)128 * 1024];
__device__ __align__(256) __half g_t_hi[(size_t)16384 * 128];
__device__ __align__(256) __half g_t_lo[(size_t)16384 * 128];
__device__ __align__(256) float g_sq[16384];

// ---------------- PTX helpers ----------------
__device__ __forceinline__ uint32_t smem_u32(const void* p) {
    uint32_t a;
    asm("{ .reg .u64 t; cvta.to.shared.u64 t, %1; cvt.u32.u64 %0, t; }" : "=r"(a) : "l"(p));
    return a;
}
__device__ __forceinline__ void cp16(uint32_t saddr, const void* g) {
    asm volatile("cp.async.cg.shared.global [%0], [%1], 16;" :: "r"(saddr), "l"(g));
}
__device__ __forceinline__ void cp_commit() {
    asm volatile("cp.async.commit_group;" ::: "memory");
}
__device__ __forceinline__ void ldsm4(uint32_t* r, uint32_t addr) {
    asm volatile("ldmatrix.sync.aligned.m8n8.x4.shared.b16 {%0,%1,%2,%3}, [%4];"
                 : "=r"(r[0]), "=r"(r[1]), "=r"(r[2]), "=r"(r[3]) : "r"(addr));
}
__device__ __forceinline__ void mma_f16(float* c, const uint32_t* a, const uint32_t* b) {
    asm volatile(
        "mma.sync.aligned.m16n8k16.row.col.f32.f16.f16.f32 "
        "{%0,%1,%2,%3}, {%4,%5,%6,%7}, {%8,%9}, {%0,%1,%2,%3};"
        : "+f"(c[0]), "+f"(c[1]), "+f"(c[2]), "+f"(c[3])
        : "r"(a[0]), "r"(a[1]), "r"(a[2]), "r"(a[3]), "r"(b[0]), "r"(b[1]));
}

// ---------------- unified tensor-core GEMM ------------------------
// acc = A @ B^T, fp16 operands, fp32 accumulate.
// MODE 0 (GEMM1): BK=64, 1 product;  C = relu(acc+bias) -> half hi
// MODE 1 (GEMM2): BK=32, 2 products; C -> hi/lo + row sumsq -> Cf
// MODE 2 (DIST):  BK=32, 3 products; SYMMETRIC: grid.x = 36 triangle pairs,
//                 writes direct block + mirrored transpose block.
// CTA tile 128x128. 8 warps as 2(m) x 4(n); warp tile 64x32.
template <int MODE>
__global__ __launch_bounds__(256, 2)
void mma_gemm(const __half* __restrict__ Ahi, const __half* __restrict__ Alo,
              const __half* __restrict__ Bhi, const __half* __restrict__ Blo,
              const float* __restrict__ bias,
              float* __restrict__ Cf,
              __half* __restrict__ Chi, __half* __restrict__ Clo,
              int K, int Ncols) {
    constexpr int NPROD = (MODE == 0) ? 1 : (MODE == 1) ? 2 : 3;
    constexpr int BK   = (MODE == 0) ? 64 : 32;
    constexpr int ROWB = BK * 2;                   // bytes per smem row
    constexpr int KS   = BK / 16;                  // k-steps per chunk
    constexpr int ASZ  = (MODE == 1) ? 8192 : 16384;
    constexpr int BSZ  = 16384;
    constexpr int STG  = ASZ + BSZ;                // 32K / 24K / 32K
    constexpr int NSTG = (MODE == 1) ? 4 : 3;
    constexpr int NITER = STG / 16 / 256;          // 8 / 6 / 8

    extern __shared__ char smem[];
    const uint32_t sbase = smem_u32(smem);
    float* sq_s = reinterpret_cast<float*>(smem + NSTG * STG);
    const int tid = threadIdx.x;
    const int lane = tid & 31;
    const int wid = tid >> 5;
    const int warp_m = wid & 1;       // 2 m-warps
    const int warp_n = wid >> 1;      // 4 n-warps

    // block coordinates (triangle unrank for MODE 2)
    int bi = blockIdx.y, bj = blockIdx.x;
    if (MODE == 2) {
        int p = blockIdx.x;
        bi = 0;
        while (p >= 8 - bi) { p -= 8 - bi; ++bi; }
        bj = bi + p;
    }
    const int mBase = (MODE == 2) ? bi * 128 : (int)blockIdx.y * 128;
    const int nBase = (MODE == 2) ? bj * 128 : (int)blockIdx.x * 128;
    const int zb = (MODE == 2) ? blockIdx.z : 0;
    const size_t zrow = (size_t)zb * 1024;
    const int NC = K / BK;

    if (MODE == 1 && tid < 128) sq_s[tid] = 0.0f;

    float acc[4][4][4];
#pragma unroll
    for (int i = 0; i < 4; i++)
#pragma unroll
        for (int j = 0; j < 4; j++)
#pragma unroll
            for (int q = 0; q < 4; q++) acc[i][j][q] = 0.0f;

    auto load_chunk = [&](int c, int stg) {
        const int k0 = c * BK;
        const uint32_t sb = sbase + stg * STG;
#pragma unroll
        for (int it = 0; it < NITER; ++it) {
            const __half* src;
            uint32_t soff;
            int rb;
            if (MODE == 0) {
                const int seg = it >> 2;           // 0=A-hi, 1=B-hi
                src = (seg == 0) ? Ahi : Bhi;
                soff = (seg == 0) ? 0u : (uint32_t)ASZ;
                rb = (seg == 0) ? mBase : nBase;
                const int l = (tid + it * 256) & 1023;
                const int row = l >> 3, sub = l & 7;
                const size_t goff = (zrow + rb + row) * (size_t)K + k0 + sub * 8;
                const uint32_t dst = sb + soff + row * 128 + ((sub ^ (row & 7)) << 4);
                cp16(dst, src + goff);
            } else {
                const int seg = it >> 1;
                if (MODE == 1) {                   // 0=A-hi 1=B-hi 2=B-lo
                    src = (seg == 0) ? Ahi : (seg == 1) ? Bhi : Blo;
                    soff = (seg == 0) ? 0u : (seg == 1) ? (uint32_t)ASZ
                                                        : (uint32_t)ASZ + 8192u;
                    rb = (seg == 0) ? mBase : nBase;
                } else {                           // 0=A-hi 1=A-lo 2=B-hi 3=B-lo
                    src = (seg == 0) ? Ahi : (seg == 1) ? Alo : (seg == 2) ? Bhi : Blo;
                    soff = (uint32_t)seg * 8192u;
                    rb = (seg < 2) ? mBase : nBase;
                }
                const int l = (tid + it * 256) & 511;
                const int row = l >> 2, sub = l & 3;
                const size_t goff = (zrow + rb + row) * (size_t)K + k0 + sub * 8;
                const uint32_t dst = sb + soff + row * 64 + (((sub + (row >> 1)) & 3) << 4);
                cp16(dst, src + goff);
            }
        }
    };

    load_chunk(0, 0); cp_commit();
#pragma unroll
    for (int s = 1; s < NSTG; ++s) {
        if (s < NC) load_chunk(s, s);
        cp_commit();
    }

    // ldmatrix per-lane components
    const int a_row_l = lane & 15;
    const int a_cs = lane >> 4;
    const int b_row_l = (lane & 7) + ((lane >> 4) << 3);
    const int b_cs = (lane >> 3) & 1;

    for (int c = 0; c < NC; ++c) {
        asm volatile("cp.async.wait_group %0;" :: "n"(NSTG - 2) : "memory");
        __syncthreads();
        const uint32_t base = sbase + (c % NSTG) * STG;
#pragma unroll
        for (int ks = 0; ks < KS; ++ks) {
            uint32_t Ah[4][4], Al[4][4];
#pragma unroll
            for (int mi = 0; mi < 4; ++mi) {
                const int row = warp_m * 64 + mi * 16 + a_row_l;
                uint32_t off;
                if (MODE == 0) off = ((ks * 2 + a_cs) ^ (a_row_l & 7)) << 4;
                else           off = ((ks * 2 + a_cs + (a_row_l >> 1)) & 3) << 4;
                const uint32_t addr = base + row * ROWB + off;
                ldsm4(Ah[mi], addr);
                if (NPROD == 3) ldsm4(Al[mi], addr + 8192);
            }
            if (ks == 0) {
                if (c + NSTG - 1 < NC) load_chunk(c + NSTG - 1, (c + NSTG - 1) % NSTG);
                cp_commit();
            }
#pragma unroll
            for (int np = 0; np < 2; ++np) {
                uint32_t Bh[4], Bl[4];
                const int n = warp_n * 32 + np * 16 + b_row_l;
                uint32_t off;
                if (MODE == 0) off = ((ks * 2 + b_cs) ^ (b_row_l & 7)) << 4;
                else           off = ((ks * 2 + b_cs + (b_row_l >> 1)) & 3) << 4;
                const uint32_t baddr = base + ASZ + n * ROWB + off;
                ldsm4(Bh, baddr);
                if (NPROD >= 2) ldsm4(Bl, baddr + 8192);
#pragma unroll
                for (int half = 0; half < 2; ++half) {
                    const uint32_t bh[2] = {Bh[half * 2], Bh[half * 2 + 1]};
#pragma unroll
                    for (int mi = 0; mi < 4; ++mi)
                        mma_f16(acc[mi][np * 2 + half], Ah[mi], bh);
                    if (NPROD >= 2) {
                        const uint32_t bl[2] = {Bl[half * 2], Bl[half * 2 + 1]};
#pragma unroll
                        for (int mi = 0; mi < 4; ++mi)
                            mma_f16(acc[mi][np * 2 + half], Ah[mi], bl);
                    }
                    if (NPROD == 3) {
#pragma unroll
                        for (int mi = 0; mi < 4; ++mi)
                            mma_f16(acc[mi][np * 2 + half], Al[mi], bh);
                    }
                }
            }
        }
    }

    // ---------------- epilogue ----------------
    if (MODE == 2) {
        const float* sqg = bias + zb * 1024;
        float* Ob = Cf + (size_t)zb * 1024 * 1024;
        const bool diag = (bi == bj);
        float* T = reinterpret_cast<float*>(smem);   // reuse stages: 128x132 fp32
        __syncthreads();                             // stages fully consumed
#pragma unroll
        for (int mi = 0; mi < 4; ++mi) {
            const int lr0 = warp_m * 64 + mi * 16 + (lane >> 2);
            const int r0 = mBase + lr0;
            const float sr0 = sqg[r0], sr1 = sqg[r0 + 8];
#pragma unroll
            for (int ni = 0; ni < 4; ++ni) {
                const int lcol = warp_n * 32 + ni * 8 + 2 * (lane & 3);
                const int col = nBase + lcol;
                const float sc0 = sqg[col], sc1 = sqg[col + 1];
                const float* cc = acc[mi][ni];
                const float v00 = fmaxf(sr0 + sc0 - 2.0f * cc[0], 0.f);
                const float v01 = fmaxf(sr0 + sc1 - 2.0f * cc[1], 0.f);
                const float v10 = fmaxf(sr1 + sc0 - 2.0f * cc[2], 0.f);
                const float v11 = fmaxf(sr1 + sc1 - 2.0f * cc[3], 0.f);
                *reinterpret_cast<float2*>(Ob + (size_t)r0 * Ncols + col) =
                    make_float2(v00, v01);
                *reinterpret_cast<float2*>(Ob + (size_t)(r0 + 8) * Ncols + col) =
                    make_float2(v10, v11);
                if (!diag) {                       // stage transpose: T[j][i]
                    T[lcol * 132 + lr0] = v00;
                    T[(lcol + 1) * 132 + lr0] = v01;
                    T[lcol * 132 + lr0 + 8] = v10;
                    T[(lcol + 1) * 132 + lr0 + 8] = v11;
                }
            }
        }
        if (!diag) {
            __syncthreads();
            // mirror block at (bj, bi): row j reads T[j][*] coalesced
#pragma unroll
            for (int it = 0; it < 4; ++it) {
                const int j = (tid >> 3) + it * 32;
                const int c0 = (tid & 7) * 4;
                float* dst = Ob + (size_t)(nBase + j) * Ncols + mBase;
#pragma unroll
                for (int cq = 0; cq < 4; ++cq) {
                    const int c = c0 + cq * 32;
                    *reinterpret_cast<float4*>(dst + c) =
                        *reinterpret_cast<const float4*>(&T[j * 132 + c]);
                }
            }
        }
    } else {
#pragma unroll
        for (int mi = 0; mi < 4; ++mi) {
            const int r0 = mBase + warp_m * 64 + mi * 16 + (lane >> 2);
            float ss0 = 0.0f, ss1 = 0.0f;
#pragma unroll
            for (int ni = 0; ni < 4; ++ni) {
                const int col = nBase + warp_n * 32 + ni * 8 + 2 * (lane & 3);
                const float bz0 = __ldg(&bias[col]), bz1 = __ldg(&bias[col + 1]);
                const float* cc = acc[mi][ni];
                const float v00 = fmaxf(cc[0] + bz0, 0.f), v01 = fmaxf(cc[1] + bz1, 0.f);
                const float v10 = fmaxf(cc[2] + bz0, 0.f), v11 = fmaxf(cc[3] + bz1, 0.f);
                if (MODE == 1) { ss0 += v00 * v00 + v01 * v01; ss1 += v10 * v10 + v11 * v11; }
                const __half h00 = __float2half_rn(v00), h01 = __float2half_rn(v01);
                const __half h10 = __float2half_rn(v10), h11 = __float2half_rn(v11);
                __half2 hp0 = __halves2half2(h00, h01);
                __half2 hp1 = __halves2half2(h10, h11);
                *reinterpret_cast<uint32_t*>(Chi + (size_t)r0 * Ncols + col) =
                    *reinterpret_cast<uint32_t*>(&hp0);
                *reinterpret_cast<uint32_t*>(Chi + (size_t)(r0 + 8) * Ncols + col) =
                    *reinterpret_cast<uint32_t*>(&hp1);
                if (MODE == 1) {
                    const __half l00 = __float2half_rn(v00 - __half2float(h00));
                    const __half l01 = __float2half_rn(v01 - __half2float(h01));
                    const __half l10 = __float2half_rn(v10 - __half2float(h10));
                    const __half l11 = __float2half_rn(v11 - __half2float(h11));
                    __half2 lp0 = __halves2half2(l00, l01);
                    __half2 lp1 = __halves2half2(l10, l11);
                    *reinterpret_cast<uint32_t*>(Clo + (size_t)r0 * Ncols + col) =
                        *reinterpret_cast<uint32_t*>(&lp0);
                    *reinterpret_cast<uint32_t*>(Clo + (size_t)(r0 + 8) * Ncols + col) =
                        *reinterpret_cast<uint32_t*>(&lp1);
                }
            }
            if (MODE == 1) {
                atomicAdd(&sq_s[r0 - mBase], ss0);
                atomicAdd(&sq_s[r0 + 8 - mBase], ss1);
            }
        }
        if (MODE == 1) {
            __syncthreads();
            if (tid < 128) Cf[mBase + tid] = sq_s[tid];
        }
    }
}

static const int SMEM_M0 = 3 * 32768 + 512;
static const int SMEM_M1 = 4 * 24576 + 512;
static const int SMEM_M2 = 3 * 32768 + 512;

// ---------------- fused conversion kernel ----------------
__global__ void prep_kernel(const float* __restrict__ batch,
                            const float* __restrict__ W1,
                            const float* __restrict__ W2,
                            __half* __restrict__ a_hi,
                            __half* __restrict__ w1t_hi,
                            __half* __restrict__ w2t_hi, __half* __restrict__ w2t_lo) {
    __shared__ float tile[32][33];
    const int b = blockIdx.x;
    const int tid = threadIdx.x;
    if (b < 16384) {
        const int i = b * 256 + tid;
        float4 v = reinterpret_cast<const float4*>(batch)[i];
        __half2 h0 = __halves2half2(__float2half_rn(v.x), __float2half_rn(v.y));
        __half2 h1 = __halves2half2(__float2half_rn(v.z), __float2half_rn(v.w));
        reinterpret_cast<uint2*>(a_hi)[i] =
            make_uint2(*reinterpret_cast<uint32_t*>(&h0), *reinterpret_cast<uint32_t*>(&h1));
        return;
    }
    const bool isW1 = (b < 16384 + 1024);
    const int idx = isW1 ? (b - 16384) : (b - 16384 - 1024);
    const int ncols = isW1 ? 1024 : 128;
    const int ntiles = ncols / 32;
    const int nb = (idx % ntiles) * 32;
    const int kb = (idx / ntiles) * 32;
    const float* W = isW1 ? W1 : W2;
    const int K = 1024;
    const int tx = tid & 31, ty = tid >> 5;   // (32, 8)
#pragma unroll
    for (int i = 0; i < 4; ++i)
        tile[ty + i * 8][tx] = W[(size_t)(kb + ty + i * 8) * ncols + nb + tx];
    __syncthreads();
#pragma unroll
    for (int i = 0; i < 4; ++i) {
        const int n = nb + ty + i * 8;
        const int k = kb + tx;
        const float v = tile[tx][ty + i * 8];
        const __half h = __float2half_rn(v);
        if (isW1) {
            w1t_hi[(size_t)n * K + k] = h;
        } else {
            w2t_hi[(size_t)n * K + k] = h;
            w2t_lo[(size_t)n * K + k] = __float2half_rn(v - __half2float(h));
        }
    }
}

// ---------------------------------------------------------------------------
extern "C" void kernel_launch(void* const* d_in, const int* in_sizes, int n_in,
                              void* d_out, int out_size) {
    const float* batch = (const float*)d_in[0];
    const float* W1    = (const float*)d_in[1];
    const float* b1    = (const float*)d_in[2];
    const float* W2    = (const float*)d_in[3];
    const float* b2    = (const float*)d_in[4];
    float* out = (float*)d_out;

    __half *a_hi, *h_hi, *w1t_hi, *w2t_hi, *w2t_lo, *t_hi, *t_lo;
    float *sq_ptr;
    cudaGetSymbolAddress((void**)&a_hi,   g_a_hi);
    cudaGetSymbolAddress((void**)&h_hi,   g_h_hi);
    cudaGetSymbolAddress((void**)&w1t_hi, g_w1t_hi);
    cudaGetSymbolAddress((void**)&w2t_hi, g_w2t_hi);
    cudaGetSymbolAddress((void**)&w2t_lo, g_w2t_lo);
    cudaGetSymbolAddress((void**)&t_hi,   g_t_hi);
    cudaGetSymbolAddress((void**)&t_lo,   g_t_lo);
    cudaGetSymbolAddress((void**)&sq_ptr, g_sq);

    cudaFuncSetAttribute(mma_gemm<0>, cudaFuncAttributeMaxDynamicSharedMemorySize, SMEM_M0);
    cudaFuncSetAttribute(mma_gemm<1>, cudaFuncAttributeMaxDynamicSharedMemorySize, SMEM_M1);
    cudaFuncSetAttribute(mma_gemm<2>, cudaFuncAttributeMaxDynamicSharedMemorySize, SMEM_M2);

    // 0) fused precision prep
    prep_kernel<<<16384 + 1024 + 128, 256>>>(batch, W1, W2, a_hi,
                                             w1t_hi, w2t_hi, w2t_lo);
    // 1) h = relu(batch @ W1 + b1) -> half hi   (BK=64, single product)
    {
        dim3 grid(H_DIM / 128, M_TOT / 128);   // (8, 128)
        mma_gemm<0><<<grid, 256, SMEM_M0>>>(
            a_hi, nullptr, w1t_hi, nullptr, b1, nullptr, h_hi, nullptr, D_DIM, H_DIM);
    }
    // 2) t = relu(h @ W2 + b2) -> half hi/lo + per-row squared norms
    {
        dim3 grid(R_DIM / 128, M_TOT / 128);   // (1, 128)
        mma_gemm<1><<<grid, 256, SMEM_M1>>>(
            h_hi, nullptr, w2t_hi, w2t_lo, b2, sq_ptr, t_hi, t_lo, H_DIM, R_DIM);
    }
    // 3) symmetric pairwise distances: 36 triangle tile pairs per batch
    {
        dim3 grid(36, 1, B_DIM);
        mma_gemm<2><<<grid, 256, SMEM_M2>>>(
            t_hi, t_lo, t_hi, t_lo, sq_ptr, out, nullptr, nullptr, R_DIM, L_DIM);
    }
}

// round 11
// speedup vs baseline: 1.8134x; 1.0352x over previous
#include <cuda_runtime.h>
#include <cuda_fp16.h>
#include <cstdint>
#include <cstddef>

// Shapes: batch[16,1024,1024] -> M=16384,K=1024 ; W1[1024,1024] ; W2[1024,128]
// out[16,1024,1024] fp32.
static const int M_TOT = 16384;
static const int D_DIM = 1024;
static const int H_DIM = 1024;
static const int R_DIM = 128;
static const int L_DIM = 1024;
static const int B_DIM = 16;

// ---- scratch (__device__ globals; no runtime allocation allowed) ----
__device__ __align__(256) __half g_a_hi[(size_t)16384 * 1024];
__device__ __align__(256) __half g_h_hi[(size_t)16384 * 1024];
__device__ __align__(256) __half g_w1t_hi[(size_t)1024 * 1024];
__device__ __align__(256) __half g_w2t_hi[(size_t)128 * 1024];
__device__ __align__(256) __half g_w2t_lo[(size_t)128 * 1024];
__device__ __align__(256) __half g_t_hi[(size_t)16384 * 128];
__device__ __align__(256) __half g_t_lo[(size_t)16384 * 128];
__device__ __align__(256) float g_sq[16384];

// ---------------- PTX helpers ----------------
__device__ __forceinline__ uint32_t smem_u32(const void* p) {
    uint32_t a;
    asm("{ .reg .u64 t; cvta.to.shared.u64 t, %1; cvt.u32.u64 %0, t; }" : "=r"(a) : "l"(p));
    return a;
}
__device__ __forceinline__ void cp16(uint32_t saddr, const void* g) {
    asm volatile("cp.async.cg.shared.global [%0], [%1], 16;" :: "r"(saddr), "l"(g));
}
__device__ __forceinline__ void cp_commit() {
    asm volatile("cp.async.commit_group;" ::: "memory");
}
__device__ __forceinline__ void ldsm4(uint32_t* r, uint32_t addr) {
    asm volatile("ldmatrix.sync.aligned.m8n8.x4.shared.b16 {%0,%1,%2,%3}, [%4];"
                 : "=r"(r[0]), "=r"(r[1]), "=r"(r[2]), "=r"(r[3]) : "r"(addr));
}
__device__ __forceinline__ void mma_f16(float* c, const uint32_t* a, const uint32_t* b) {
    asm volatile(
        "mma.sync.aligned.m16n8k16.row.col.f32.f16.f16.f32 "
        "{%0,%1,%2,%3}, {%4,%5,%6,%7}, {%8,%9}, {%0,%1,%2,%3};"
        : "+f"(c[0]), "+f"(c[1]), "+f"(c[2]), "+f"(c[3])
        : "r"(a[0]), "r"(a[1]), "r"(a[2]), "r"(a[3]), "r"(b[0]), "r"(b[1]));
}

// ---------------- unified tensor-core GEMM ------------------------
// acc = A @ B^T, fp16 operands, fp32 accumulate.
// MODE 0 (GEMM1): BM=128, BK=64, 1 product;  C = relu(acc+bias) -> half hi
// MODE 1 (GEMM2): BM=64,  BK=32, 2 products; C -> hi/lo + row sumsq -> Cf
// MODE 2 (DIST):  BM=128, BK=32, 2 products; SYMMETRIC 36 triangle pairs;
//                 writes direct block + mirrored transpose block.
// 8 warps as 2(m) x 4(n); warp tile (BM/2) x 32.
template <int MODE>
__global__ __launch_bounds__(256, 2)
void mma_gemm(const __half* __restrict__ Ahi,
              const __half* __restrict__ Bhi, const __half* __restrict__ Blo,
              const float* __restrict__ bias,
              float* __restrict__ Cf,
              __half* __restrict__ Chi, __half* __restrict__ Clo,
              int K, int Ncols) {
    constexpr int NPROD = (MODE == 0) ? 1 : 2;
    constexpr int MI   = (MODE == 1) ? 2 : 4;      // 16-row frags per warp
    constexpr int BM   = MI * 32;
    constexpr int BK   = (MODE == 0) ? 64 : 32;
    constexpr int ROWB = BK * 2;
    constexpr int KS   = BK / 16;
    constexpr int ASZ  = BM * ROWB;                // 16K / 4K / 8K
    constexpr int BSZ  = (NPROD == 2) ? 2 * 128 * ROWB : 128 * ROWB;
    constexpr int STG  = ASZ + BSZ;                // 32K / 20K / 24K
    constexpr int NSTG = (MODE == 0) ? 3 : 4;
    constexpr int NITER = STG / 16 / 256;          // 8 / 5 / 6

    extern __shared__ char smem[];
    const uint32_t sbase = smem_u32(smem);
    float* sq_s = reinterpret_cast<float*>(smem + NSTG * STG);
    const int tid = threadIdx.x;
    const int lane = tid & 31;
    const int wid = tid >> 5;
    const int warp_m = wid & 1;
    const int warp_n = wid >> 1;

    // block coordinates (triangle unrank for MODE 2)
    int bi = blockIdx.y, bj = blockIdx.x;
    if (MODE == 2) {
        int p = blockIdx.x;
        bi = 0;
        while (p >= 8 - bi) { p -= 8 - bi; ++bi; }
        bj = bi + p;
    }
    const int mBase = (MODE == 2) ? bi * 128 : (int)blockIdx.y * BM;
    const int nBase = (MODE == 2) ? bj * 128 : (int)blockIdx.x * 128;
    const int zb = (MODE == 2) ? blockIdx.z : 0;
    const size_t zrow = (size_t)zb * 1024;
    const int NC = K / BK;

    if (MODE == 1 && tid < BM) sq_s[tid] = 0.0f;

    float acc[MI][4][4];
#pragma unroll
    for (int i = 0; i < MI; i++)
#pragma unroll
        for (int j = 0; j < 4; j++)
#pragma unroll
            for (int q = 0; q < 4; q++) acc[i][j][q] = 0.0f;

    auto load_chunk = [&](int c, int stg) {
        const int k0 = c * BK;
        const uint32_t sb = sbase + stg * STG;
#pragma unroll
        for (int it = 0; it < NITER; ++it) {
            if (MODE == 0) {
                const int seg = it >> 2;           // 0=A-hi, 1=B-hi
                const __half* src = (seg == 0) ? Ahi : Bhi;
                const uint32_t soff = (seg == 0) ? 0u : (uint32_t)ASZ;
                const int rb = (seg == 0) ? mBase : nBase;
                const int l = (tid + it * 256) & 1023;
                const int row = l >> 3, sub = l & 7;
                const size_t goff = (zrow + rb + row) * (size_t)K + k0 + sub * 8;
                const uint32_t dst = sb + soff + row * 128 + ((sub ^ (row & 7)) << 4);
                cp16(dst, src + goff);
            } else if (MODE == 1) {
                // it0 = A-hi (256 chunks); it1-2 = B-hi; it3-4 = B-lo
                const __half* src = (it == 0) ? Ahi : (it <= 2) ? Bhi : Blo;
                const uint32_t soff = (it == 0) ? 0u
                                     : (it <= 2) ? (uint32_t)ASZ
                                                 : (uint32_t)ASZ + 8192u;
                const int rb = (it == 0) ? mBase : nBase;
                const int l = (it == 0) ? tid
                            : (it <= 2) ? (tid + (it - 1) * 256)
                                        : (tid + (it - 3) * 256);
                const int row = l >> 2, sub = l & 3;
                const size_t goff = (zrow + rb + row) * (size_t)K + k0 + sub * 8;
                const uint32_t dst = sb + soff + row * 64 + (((sub + (row >> 1)) & 3) << 4);
                cp16(dst, src + goff);
            } else {
                // it0-1 = A-hi; it2-3 = B-hi; it4-5 = B-lo
                const int seg = it >> 1;
                const __half* src = (seg == 0) ? Ahi : (seg == 1) ? Bhi : Blo;
                const uint32_t soff = (seg == 0) ? 0u
                                     : (seg == 1) ? (uint32_t)ASZ
                                                  : (uint32_t)ASZ + 8192u;
                const int rb = (seg == 0) ? mBase : nBase;
                const int l = (tid + it * 256) & 511;
                const int row = l >> 2, sub = l & 3;
                const size_t goff = (zrow + rb + row) * (size_t)K + k0 + sub * 8;
                const uint32_t dst = sb + soff + row * 64 + (((sub + (row >> 1)) & 3) << 4);
                cp16(dst, src + goff);
            }
        }
    };

    load_chunk(0, 0); cp_commit();
#pragma unroll
    for (int s = 1; s < NSTG; ++s) {
        if (s < NC) load_chunk(s, s);
        cp_commit();
    }

    // ldmatrix per-lane components
    const int a_row_l = lane & 15;
    const int a_cs = lane >> 4;
    const int b_row_l = (lane & 7) + ((lane >> 4) << 3);
    const int b_cs = (lane >> 3) & 1;

    for (int c = 0; c < NC; ++c) {
        asm volatile("cp.async.wait_group %0;" :: "n"(NSTG - 2) : "memory");
        __syncthreads();
        const uint32_t base = sbase + (c % NSTG) * STG;
#pragma unroll
        for (int ks = 0; ks < KS; ++ks) {
            uint32_t Ah[MI][4];
#pragma unroll
            for (int mi = 0; mi < MI; ++mi) {
                const int row = warp_m * (BM / 2) + mi * 16 + a_row_l;
                uint32_t off;
                if (MODE == 0) off = ((ks * 2 + a_cs) ^ (a_row_l & 7)) << 4;
                else           off = ((ks * 2 + a_cs + (a_row_l >> 1)) & 3) << 4;
                ldsm4(Ah[mi], base + row * ROWB + off);
            }
            if (ks == 0) {
                if (c + NSTG - 1 < NC) load_chunk(c + NSTG - 1, (c + NSTG - 1) % NSTG);
                cp_commit();
            }
#pragma unroll
            for (int np = 0; np < 2; ++np) {
                uint32_t Bh[4], Bl[4];
                const int n = warp_n * 32 + np * 16 + b_row_l;
                uint32_t off;
                if (MODE == 0) off = ((ks * 2 + b_cs) ^ (b_row_l & 7)) << 4;
                else           off = ((ks * 2 + b_cs + (b_row_l >> 1)) & 3) << 4;
                const uint32_t baddr = base + ASZ + n * ROWB + off;
                ldsm4(Bh, baddr);
                if (NPROD == 2) ldsm4(Bl, baddr + 8192);
#pragma unroll
                for (int half = 0; half < 2; ++half) {
                    const uint32_t bh[2] = {Bh[half * 2], Bh[half * 2 + 1]};
#pragma unroll
                    for (int mi = 0; mi < MI; ++mi)
                        mma_f16(acc[mi][np * 2 + half], Ah[mi], bh);
                    if (NPROD == 2) {
                        const uint32_t bl[2] = {Bl[half * 2], Bl[half * 2 + 1]};
#pragma unroll
                        for (int mi = 0; mi < MI; ++mi)
                            mma_f16(acc[mi][np * 2 + half], Ah[mi], bl);
                    }
                }
            }
        }
    }

    // ---------------- epilogue ----------------
    if (MODE == 2) {
        const float* sqg = bias + zb * 1024;
        float* Ob = Cf + (size_t)zb * 1024 * 1024;
        const bool diag = (bi == bj);
        float* T = reinterpret_cast<float*>(smem);   // reuse stages: 128x132 fp32
        __syncthreads();                             // stages fully consumed
#pragma unroll
        for (int mi = 0; mi < MI; ++mi) {
            const int lr0 = warp_m * 64 + mi * 16 + (lane >> 2);
            const int r0 = mBase + lr0;
            const float sr0 = sqg[r0], sr1 = sqg[r0 + 8];
#pragma unroll
            for (int ni = 0; ni < 4; ++ni) {
                const int lcol = warp_n * 32 + ni * 8 + 2 * (lane & 3);
                const int col = nBase + lcol;
                const float sc0 = sqg[col], sc1 = sqg[col + 1];
                const float* cc = acc[mi][ni];
                const float v00 = fmaxf(sr0 + sc0 - 2.0f * cc[0], 0.f);
                const float v01 = fmaxf(sr0 + sc1 - 2.0f * cc[1], 0.f);
                const float v10 = fmaxf(sr1 + sc0 - 2.0f * cc[2], 0.f);
                const float v11 = fmaxf(sr1 + sc1 - 2.0f * cc[3], 0.f);
                *reinterpret_cast<float2*>(Ob + (size_t)r0 * Ncols + col) =
                    make_float2(v00, v01);
                *reinterpret_cast<float2*>(Ob + (size_t)(r0 + 8) * Ncols + col) =
                    make_float2(v10, v11);
                if (!diag) {
                    T[lcol * 132 + lr0] = v00;
                    T[(lcol + 1) * 132 + lr0] = v01;
                    T[lcol * 132 + lr0 + 8] = v10;
                    T[(lcol + 1) * 132 + lr0 + 8] = v11;
                }
            }
        }
        if (!diag) {
            __syncthreads();
#pragma unroll
            for (int it = 0; it < 4; ++it) {
                const int j = (tid >> 3) + it * 32;
                const int c0 = (tid & 7) * 4;
                float* dst = Ob + (size_t)(nBase + j) * Ncols + mBase;
#pragma unroll
                for (int cq = 0; cq < 4; ++cq) {
                    const int c = c0 + cq * 32;
                    *reinterpret_cast<float4*>(dst + c) =
                        *reinterpret_cast<const float4*>(&T[j * 132 + c]);
                }
            }
        }
    } else {
#pragma unroll
        for (int mi = 0; mi < MI; ++mi) {
            const int r0 = mBase + warp_m * (BM / 2) + mi * 16 + (lane >> 2);
            float ss0 = 0.0f, ss1 = 0.0f;
#pragma unroll
            for (int ni = 0; ni < 4; ++ni) {
                const int col = nBase + warp_n * 32 + ni * 8 + 2 * (lane & 3);
                const float bz0 = __ldg(&bias[col]), bz1 = __ldg(&bias[col + 1]);
                const float* cc = acc[mi][ni];
                const float v00 = fmaxf(cc[0] + bz0, 0.f), v01 = fmaxf(cc[1] + bz1, 0.f);
                const float v10 = fmaxf(cc[2] + bz0, 0.f), v11 = fmaxf(cc[3] + bz1, 0.f);
                if (MODE == 1) { ss0 += v00 * v00 + v01 * v01; ss1 += v10 * v10 + v11 * v11; }
                const __half h00 = __float2half_rn(v00), h01 = __float2half_rn(v01);
                const __half h10 = __float2half_rn(v10), h11 = __float2half_rn(v11);
                __half2 hp0 = __halves2half2(h00, h01);
                __half2 hp1 = __halves2half2(h10, h11);
                *reinterpret_cast<uint32_t*>(Chi + (size_t)r0 * Ncols + col) =
                    *reinterpret_cast<uint32_t*>(&hp0);
                *reinterpret_cast<uint32_t*>(Chi + (size_t)(r0 + 8) * Ncols + col) =
                    *reinterpret_cast<uint32_t*>(&hp1);
                if (MODE == 1) {
                    const __half l00 = __float2half_rn(v00 - __half2float(h00));
                    const __half l01 = __float2half_rn(v01 - __half2float(h01));
                    const __half l10 = __float2half_rn(v10 - __half2float(h10));
                    const __half l11 = __float2half_rn(v11 - __half2float(h11));
                    __half2 lp0 = __halves2half2(l00, l01);
                    __half2 lp1 = __halves2half2(l10, l11);
                    *reinterpret_cast<uint32_t*>(Clo + (size_t)r0 * Ncols + col) =
                        *reinterpret_cast<uint32_t*>(&lp0);
                    *reinterpret_cast<uint32_t*>(Clo + (size_t)(r0 + 8) * Ncols + col) =
                        *reinterpret_cast<uint32_t*>(&lp1);
                }
            }
            if (MODE == 1) {
                atomicAdd(&sq_s[r0 - mBase], ss0);
                atomicAdd(&sq_s[r0 + 8 - mBase], ss1);
            }
        }
        if (MODE == 1) {
            __syncthreads();
            if (tid < BM) Cf[mBase + tid] = sq_s[tid];
        }
    }
}

static const int SMEM_M0 = 3 * 32768 + 512;   // 98816
static const int SMEM_M1 = 4 * 20480 + 512;   // 82432
static const int SMEM_M2 = 4 * 24576 + 512;   // 98816

// ---------------- fused conversion kernel ----------------
__global__ void prep_kernel(const float* __restrict__ batch,
                            const float* __restrict__ W1,
                            const float* __restrict__ W2,
                            __half* __restrict__ a_hi,
                            __half* __restrict__ w1t_hi,
                            __half* __restrict__ w2t_hi, __half* __restrict__ w2t_lo) {
    __shared__ float tile[32][33];
    const int b = blockIdx.x;
    const int tid = threadIdx.x;
    if (b < 16384) {
        const int i = b * 256 + tid;
        float4 v = reinterpret_cast<const float4*>(batch)[i];
        __half2 h0 = __halves2half2(__float2half_rn(v.x), __float2half_rn(v.y));
        __half2 h1 = __halves2half2(__float2half_rn(v.z), __float2half_rn(v.w));
        reinterpret_cast<uint2*>(a_hi)[i] =
            make_uint2(*reinterpret_cast<uint32_t*>(&h0), *reinterpret_cast<uint32_t*>(&h1));
        return;
    }
    const bool isW1 = (b < 16384 + 1024);
    const int idx = isW1 ? (b - 16384) : (b - 16384 - 1024);
    const int ncols = isW1 ? 1024 : 128;
    const int ntiles = ncols / 32;
    const int nb = (idx % ntiles) * 32;
    const int kb = (idx / ntiles) * 32;
    const float* W = isW1 ? W1 : W2;
    const int K = 1024;
    const int tx = tid & 31, ty = tid >> 5;   // (32, 8)
#pragma unroll
    for (int i = 0; i < 4; ++i)
        tile[ty + i * 8][tx] = W[(size_t)(kb + ty + i * 8) * ncols + nb + tx];
    __syncthreads();
#pragma unroll
    for (int i = 0; i < 4; ++i) {
        const int n = nb + ty + i * 8;
        const int k = kb + tx;
        const float v = tile[tx][ty + i * 8];
        const __half h = __float2half_rn(v);
        if (isW1) {
            w1t_hi[(size_t)n * K + k] = h;
        } else {
            w2t_hi[(size_t)n * K + k] = h;
            w2t_lo[(size_t)n * K + k] = __float2half_rn(v - __half2float(h));
        }
    }
}

// ---------------------------------------------------------------------------
extern "C" void kernel_launch(void* const* d_in, const int* in_sizes, int n_in,
                              void* d_out, int out_size) {
    const float* batch = (const float*)d_in[0];
    const float* W1    = (const float*)d_in[1];
    const float* b1    = (const float*)d_in[2];
    const float* W2    = (const float*)d_in[3];
    const float* b2    = (const float*)d_in[4];
    float* out = (float*)d_out;

    __half *a_hi, *h_hi, *w1t_hi, *w2t_hi, *w2t_lo, *t_hi, *t_lo;
    float *sq_ptr;
    cudaGetSymbolAddress((void**)&a_hi,   g_a_hi);
    cudaGetSymbolAddress((void**)&h_hi,   g_h_hi);
    cudaGetSymbolAddress((void**)&w1t_hi, g_w1t_hi);
    cudaGetSymbolAddress((void**)&w2t_hi, g_w2t_hi);
    cudaGetSymbolAddress((void**)&w2t_lo, g_w2t_lo);
    cudaGetSymbolAddress((void**)&t_hi,   g_t_hi);
    cudaGetSymbolAddress((void**)&t_lo,   g_t_lo);
    cudaGetSymbolAddress((void**)&sq_ptr, g_sq);

    cudaFuncSetAttribute(mma_gemm<0>, cudaFuncAttributeMaxDynamicSharedMemorySize, SMEM_M0);
    cudaFuncSetAttribute(mma_gemm<1>, cudaFuncAttributeMaxDynamicSharedMemorySize, SMEM_M1);
    cudaFuncSetAttribute(mma_gemm<2>, cudaFuncAttributeMaxDynamicSharedMemorySize, SMEM_M2);

    // 0) fused precision prep
    prep_kernel<<<16384 + 1024 + 128, 256>>>(batch, W1, W2, a_hi,
                                             w1t_hi, w2t_hi, w2t_lo);
    // 1) h = relu(batch @ W1 + b1) -> half hi   (BK=64, single product)
    {
        dim3 grid(H_DIM / 128, M_TOT / 128);   // (8, 128)
        mma_gemm<0><<<grid, 256, SMEM_M0>>>(
            a_hi, w1t_hi, nullptr, b1, nullptr, h_hi, nullptr, D_DIM, H_DIM);
    }
    // 2) t = relu(h @ W2 + b2) -> half hi/lo + row sumsq   (BM=64: 256 CTAs)
    {
        dim3 grid(R_DIM / 128, M_TOT / 64);    // (1, 256)
        mma_gemm<1><<<grid, 256, SMEM_M1>>>(
            h_hi, w2t_hi, w2t_lo, b2, sq_ptr, t_hi, t_lo, H_DIM, R_DIM);
    }
    // 3) symmetric pairwise distances: 36 triangle tile pairs per batch
    {
        dim3 grid(36, 1, B_DIM);
        mma_gemm<2><<<grid, 256, SMEM_M2>>>(
            t_hi, t_hi, t_lo, sq_ptr, out, nullptr, nullptr, R_DIM, L_DIM);
    }
}